// round 4
// baseline (speedup 1.0000x reference)
#include <cuda_runtime.h>
#include <math.h>

// Problem constants
#define BB     4
#define SEQ_N  1024
#define SEQ_M  2048
#define CH     768
#define NH     12
#define HD     64
#define KDIM   768
#define QSCALE 0.125f
#define NEGV   -9e15f

// Scratch (device globals: allocation-free rule)
__device__ __align__(256) float g_Qp[BB*NH*SEQ_N*HD];   // [B,H,N,d]  (pre-scaled)
__device__ __align__(256) float g_K [BB*NH*SEQ_M*HD];   // [B,H,M,d]
__device__ __align__(256) float g_V [BB*NH*SEQ_M*HD];   // [B,H,M,d]
__device__ __align__(256) float g_X [BB*SEQ_N*CH];      // attention out [B,N,C]

// ---------------------------------------------------------------------------
// Generic 64x64-tile fp32 GEMM:  out[r,o] = sum_k A[r,k] * W[o,k]
// mode 0: Q proj   -> g_Qp[b,h,n,d] * QSCALE      (rows = B*N, cols = 768)
// mode 1: KV proj  -> g_K / g_V [b,h,m,d]         (rows = B*M, cols = 1536)
// mode 2: out proj -> out[r*CH+o] = acc + bias[o] (rows = B*N, cols = 768, A = g_X)
// ---------------------------------------------------------------------------
__global__ __launch_bounds__(256)
void gemm64_kernel(const float* __restrict__ A, const float* __restrict__ W,
                   int mode, float* __restrict__ out, const float* __restrict__ bias)
{
    __shared__ float As[64 * 20];
    __shared__ float Ws[64 * 20];

    const int tid = threadIdx.x;
    const int ty  = tid >> 4;       // 0..15
    const int tx  = tid & 15;       // 0..15
    const int rowBase = blockIdx.y * 64;
    const int oBase   = blockIdx.x * 64;

    const int lr = tid >> 2;        // 0..63 : tile row this thread loads
    const int lc = (tid & 3) * 4;   // 0,4,8,12 : k offset this thread loads

    const float* Ap = (mode == 2) ? g_X : A;

    float acc[4][4];
#pragma unroll
    for (int i = 0; i < 4; i++)
#pragma unroll
        for (int j = 0; j < 4; j++) acc[i][j] = 0.f;

    const float* Arow = Ap + (size_t)(rowBase + lr) * KDIM + lc;
    const float* Wrow = W  + (size_t)(oBase   + lr) * KDIM + lc;

#pragma unroll 1
    for (int kt = 0; kt < KDIM; kt += 16) {
        __syncthreads();
        float4 a4 = *(const float4*)(Arow + kt);
        float4 w4 = *(const float4*)(Wrow + kt);
        *(float4*)&As[lr * 20 + lc] = a4;
        *(float4*)&Ws[lr * 20 + lc] = w4;
        __syncthreads();

#pragma unroll
        for (int kk = 0; kk < 16; kk += 4) {
            float4 av[4], wv[4];
#pragma unroll
            for (int i = 0; i < 4; i++) av[i] = *(float4*)&As[(ty*4 + i)*20 + kk];
#pragma unroll
            for (int j = 0; j < 4; j++) wv[j] = *(float4*)&Ws[(tx*4 + j)*20 + kk];
#pragma unroll
            for (int i = 0; i < 4; i++)
#pragma unroll
                for (int j = 0; j < 4; j++)
                    acc[i][j] += av[i].x*wv[j].x + av[i].y*wv[j].y
                               + av[i].z*wv[j].z + av[i].w*wv[j].w;
        }
    }

    if (mode == 0) {
        // o-block of 64 == exactly one head (64 | oBase)
        const int h = oBase / HD;
#pragma unroll
        for (int i = 0; i < 4; i++) {
            const int r = rowBase + ty*4 + i;
            const int b = r / SEQ_N, n = r % SEQ_N;
            float4 v = make_float4(acc[i][0]*QSCALE, acc[i][1]*QSCALE,
                                   acc[i][2]*QSCALE, acc[i][3]*QSCALE);
            *(float4*)(g_Qp + (((size_t)(b*NH + h)*SEQ_N + n)*HD) + tx*4) = v;
        }
    } else if (mode == 1) {
        const int jkv = oBase / CH;           // 0 = K, 1 = V (block never straddles)
        const int h   = (oBase % CH) / HD;
        float* dstBase = jkv ? g_V : g_K;
#pragma unroll
        for (int i = 0; i < 4; i++) {
            const int r = rowBase + ty*4 + i;
            const int b = r / SEQ_M, m = r % SEQ_M;
            float4 v = make_float4(acc[i][0], acc[i][1], acc[i][2], acc[i][3]);
            *(float4*)(dstBase + (((size_t)(b*NH + h)*SEQ_M + m)*HD) + tx*4) = v;
        }
    } else {
        float4 bi = *(const float4*)(bias + oBase + tx*4);
#pragma unroll
        for (int i = 0; i < 4; i++) {
            const int r = rowBase + ty*4 + i;
            float4 v = make_float4(acc[i][0]+bi.x, acc[i][1]+bi.y,
                                   acc[i][2]+bi.z, acc[i][3]+bi.w);
            *(float4*)(out + (size_t)r*CH + oBase + tx*4) = v;
        }
    }
}

// ---------------------------------------------------------------------------
// Flash attention: per (b,h, 64-row n-tile) block. Online softmax over M.
// grid = (N/64, B*H), 256 threads, dynamic smem = 4 * 64*68 floats = 69632 B.
// ---------------------------------------------------------------------------
#define FA_SMEM (4 * 64 * 68 * (int)sizeof(float))

__global__ __launch_bounds__(256, 2)
void flash_kernel(const int* __restrict__ mask)
{
    extern __shared__ float sm[];
    float* Qs = sm;                // [64][68]
    float* Ks = sm + 64*68;
    float* Vs = sm + 2*64*68;
    float* Ps = sm + 3*64*68;

    const int tid = threadIdx.x;
    const int ty  = tid >> 4;
    const int tx  = tid & 15;
    const int bh  = blockIdx.y;
    const int b   = bh / NH, h = bh % NH;
    const int n0  = blockIdx.x * 64;

    // Load Q tile [64 x 64]
    {
        const float* Qg = g_Qp + ((size_t)bh*SEQ_N + n0)*HD;
        for (int idx = tid; idx < 64*16; idx += 256) {
            int r = idx >> 4, c4 = (idx & 15) * 4;
            *(float4*)&Qs[r*68 + c4] = *(const float4*)(Qg + r*HD + c4);
        }
    }

    float m_i[4], l_i[4], o[4][4];
#pragma unroll
    for (int i = 0; i < 4; i++) {
        m_i[i] = -INFINITY; l_i[i] = 0.f;
#pragma unroll
        for (int j = 0; j < 4; j++) o[i][j] = 0.f;
    }

    const int* maskBase = mask + ((size_t)b*SEQ_N + n0)*SEQ_M;

    for (int mt = 0; mt < SEQ_M; mt += 64) {
        __syncthreads();   // previous PV done before K/V/P overwrite
        {
            const float* Kg = g_K + ((size_t)bh*SEQ_M + mt)*HD;
            const float* Vg = g_V + ((size_t)bh*SEQ_M + mt)*HD;
            for (int idx = tid; idx < 64*16; idx += 256) {
                int r = idx >> 4, c4 = (idx & 15) * 4;
                *(float4*)&Ks[r*68 + c4] = *(const float4*)(Kg + r*HD + c4);
                *(float4*)&Vs[r*68 + c4] = *(const float4*)(Vg + r*HD + c4);
            }
        }
        __syncthreads();

        // S = (Q*scale) @ K^T  -- 4x4 micro-tile per thread
        float s[4][4];
#pragma unroll
        for (int i = 0; i < 4; i++)
#pragma unroll
            for (int j = 0; j < 4; j++) s[i][j] = 0.f;

#pragma unroll 8
        for (int dd = 0; dd < 64; dd += 4) {
            float4 qv[4], kv[4];
#pragma unroll
            for (int i = 0; i < 4; i++) qv[i] = *(float4*)&Qs[(ty*4 + i)*68 + dd];
#pragma unroll
            for (int j = 0; j < 4; j++) kv[j] = *(float4*)&Ks[(tx*4 + j)*68 + dd];
#pragma unroll
            for (int i = 0; i < 4; i++)
#pragma unroll
                for (int j = 0; j < 4; j++)
                    s[i][j] += qv[i].x*kv[j].x + qv[i].y*kv[j].y
                             + qv[i].z*kv[j].z + qv[i].w*kv[j].w;
        }

        // Mask (int4 straight from gmem)
#pragma unroll
        for (int i = 0; i < 4; i++) {
            int4 mk = *(const int4*)(maskBase + (size_t)(ty*4 + i)*SEQ_M + mt + tx*4);
            if (mk.x == 0) s[i][0] = NEGV;
            if (mk.y == 0) s[i][1] = NEGV;
            if (mk.z == 0) s[i][2] = NEGV;
            if (mk.w == 0) s[i][3] = NEGV;
        }

        // Online softmax update (row reduce across the 16 tx lanes)
#pragma unroll
        for (int i = 0; i < 4; i++) {
            float tm = fmaxf(fmaxf(s[i][0], s[i][1]), fmaxf(s[i][2], s[i][3]));
#pragma unroll
            for (int off = 8; off > 0; off >>= 1)
                tm = fmaxf(tm, __shfl_xor_sync(0xffffffffu, tm, off));
            float mn = fmaxf(m_i[i], tm);
            float ts = 0.f;
#pragma unroll
            for (int j = 0; j < 4; j++) {
                float p = __expf(s[i][j] - mn);
                s[i][j] = p;
                ts += p;
            }
#pragma unroll
            for (int off = 8; off > 0; off >>= 1)
                ts += __shfl_xor_sync(0xffffffffu, ts, off);
            float corr = __expf(m_i[i] - mn);
            l_i[i] = l_i[i]*corr + ts;
            m_i[i] = mn;
#pragma unroll
            for (int j = 0; j < 4; j++) o[i][j] *= corr;
            *(float4*)&Ps[(ty*4 + i)*68 + tx*4] = make_float4(s[i][0], s[i][1], s[i][2], s[i][3]);
        }
        __syncthreads();

        // O += P @ V
#pragma unroll 4
        for (int mm = 0; mm < 64; mm += 4) {
            float4 vv0 = *(float4*)&Vs[(mm+0)*68 + tx*4];
            float4 vv1 = *(float4*)&Vs[(mm+1)*68 + tx*4];
            float4 vv2 = *(float4*)&Vs[(mm+2)*68 + tx*4];
            float4 vv3 = *(float4*)&Vs[(mm+3)*68 + tx*4];
#pragma unroll
            for (int i = 0; i < 4; i++) {
                float4 pv = *(float4*)&Ps[(ty*4 + i)*68 + mm];
                o[i][0] += pv.x*vv0.x + pv.y*vv1.x + pv.z*vv2.x + pv.w*vv3.x;
                o[i][1] += pv.x*vv0.y + pv.y*vv1.y + pv.z*vv2.y + pv.w*vv3.y;
                o[i][2] += pv.x*vv0.z + pv.y*vv1.z + pv.z*vv2.z + pv.w*vv3.z;
                o[i][3] += pv.x*vv0.w + pv.y*vv1.w + pv.z*vv2.w + pv.w*vv3.w;
            }
        }
    }

    // Normalize + write X[b, n, h*64 + d]
#pragma unroll
    for (int i = 0; i < 4; i++) {
        float inv = 1.f / l_i[i];
        float4 v = make_float4(o[i][0]*inv, o[i][1]*inv, o[i][2]*inv, o[i][3]*inv);
        *(float4*)(g_X + ((size_t)(b*SEQ_N + n0 + ty*4 + i))*CH + h*HD + tx*4) = v;
    }
}

// ---------------------------------------------------------------------------
extern "C" void kernel_launch(void* const* d_in, const int* in_sizes, int n_in,
                              void* d_out, int out_size)
{
    const float* q     = (const float*)d_in[0];   // [4,1024,768]
    const float* kv    = (const float*)d_in[1];   // [4,2048,768]
    const float* Wq    = (const float*)d_in[2];   // [768,768]
    const float* Wkv   = (const float*)d_in[3];   // [1536,768]
    const float* Wproj = (const float*)d_in[4];   // [768,768]
    const float* bproj = (const float*)d_in[5];   // [768]
    const int*   mask  = (const int*)d_in[6];     // [4,1,1024,2048]
    float* out = (float*)d_out;                   // [4,1024,768]

    // Idempotent; executes on the pre-capture correctness call so the captured
    // launches already see the raised smem limit.
    cudaFuncSetAttribute(flash_kernel,
                         cudaFuncAttributeMaxDynamicSharedMemorySize, FA_SMEM);

    // Q projection: rows = B*N = 4096, cols = 768
    gemm64_kernel<<<dim3(CH/64, (BB*SEQ_N)/64), 256>>>(q, Wq, 0, nullptr, nullptr);
    // KV projection: rows = B*M = 8192, cols = 1536
    gemm64_kernel<<<dim3((2*CH)/64, (BB*SEQ_M)/64), 256>>>(kv, Wkv, 1, nullptr, nullptr);
    // Fused masked-softmax attention
    flash_kernel<<<dim3(SEQ_N/64, BB*NH), 256, FA_SMEM>>>(mask);
    // Output projection + bias
    gemm64_kernel<<<dim3(CH/64, (BB*SEQ_N)/64), 256>>>(nullptr, Wproj, 2, out, bproj);
}

// round 5
// speedup vs baseline: 2.7617x; 2.7617x over previous
#include <cuda_runtime.h>
#include <math.h>
#include <stdint.h>

// Problem constants
#define BB     4
#define SEQ_N  1024
#define SEQ_M  2048
#define CH     768
#define NH     12
#define HD     64
#define QSCALE 0.125f
#define NEGV   -9e15f

// Scratch (device globals: allocation-free rule)
__device__ __align__(256) float g_Qp[BB*NH*SEQ_N*HD];   // [B,H,N,d] pre-scaled fp32
__device__ __align__(256) float g_K [BB*NH*SEQ_M*HD];   // [B,H,M,d]
__device__ __align__(256) float g_V [BB*NH*SEQ_M*HD];   // [B,H,M,d]
__device__ __align__(256) float g_X [BB*SEQ_N*CH];      // attention out [B,N,C]

// ---------------------------------------------------------------------------
// tf32 helpers: 3xTF32 split (hi = rna(x), lo = rna(x - hi)) + m16n8k8 mma
// ---------------------------------------------------------------------------
__device__ __forceinline__ uint32_t f2tf(float x) {
    uint32_t r; asm("cvt.rna.tf32.f32 %0, %1;" : "=r"(r) : "f"(x)); return r;
}
__device__ __forceinline__ void split1(float x, uint32_t& h, uint32_t& l) {
    h = f2tf(x);
    l = f2tf(x - __uint_as_float(h));
}
__device__ __forceinline__ void mma8(float* c, const uint32_t* a, const uint32_t* b) {
    asm volatile(
        "mma.sync.aligned.m16n8k8.row.col.f32.tf32.tf32.f32 "
        "{%0,%1,%2,%3}, {%4,%5,%6,%7}, {%8,%9}, {%0,%1,%2,%3};"
        : "+f"(c[0]), "+f"(c[1]), "+f"(c[2]), "+f"(c[3])
        : "r"(a[0]), "r"(a[1]), "r"(a[2]), "r"(a[3]), "r"(b[0]), "r"(b[1]));
}
// full-precision product via 3 tf32 mmas
__device__ __forceinline__ void mma3(float* c, const uint32_t* ah, const uint32_t* al,
                                     const uint32_t* bh, const uint32_t* bl) {
    mma8(c, ah, bh);
    mma8(c, ah, bl);
    mma8(c, al, bh);
}

__device__ __forceinline__ void cp16(uint32_t dst, const void* src) {
    asm volatile("cp.async.cg.shared.global [%0], [%1], 16;" :: "r"(dst), "l"(src));
}
#define CP_COMMIT() asm volatile("cp.async.commit_group;")
#define CP_WAIT(n)  asm volatile("cp.async.wait_group %0;" :: "n"(n))

// ---------------------------------------------------------------------------
// Projection GEMM:  out[r,o] = sum_k A[r,k] * W[o,k]   (K = 768)
// Block tile 128(m) x 64(n), 256 threads = 8 warps (4m x 2n), BK = 16,
// cp.async double-buffered. 3xTF32 split done in registers at frag load.
// mode 0: Q proj  -> g_Qp * QSCALE    mode 1: KV proj -> g_K / g_V
// mode 2: out proj (A = g_X) -> out + bias
// ---------------------------------------------------------------------------
#define APITCH 20
__global__ __launch_bounds__(256)
void gemm_mma(const float* __restrict__ Ain, const float* __restrict__ W,
              int mode, float* __restrict__ out, const float* __restrict__ bias)
{
    __shared__ float As[2][128 * APITCH];
    __shared__ float Ws[2][64 * APITCH];

    const int tid  = threadIdx.x;
    const int warp = tid >> 5, lane = tid & 31;
    const int wm = warp >> 1, wn = warp & 1;
    const int g  = lane >> 2, tg = lane & 3;
    const int rowBase = blockIdx.y * 128;
    const int oBase   = blockIdx.x * 64;
    const float* A = (mode == 2) ? g_X : Ain;

    // loader geometry: A -> 2 float4/thread (same row), W -> 1 float4/thread
    const int arow = tid >> 1, acol = (tid & 1) * 8;
    const int wrow = tid >> 2, wcol = (tid & 3) * 4;
    const float* aSrc = A + (size_t)(rowBase + arow) * CH + acol;
    const float* wSrc = W + (size_t)(oBase + wrow) * CH + wcol;

    float acc[2][4][4];
#pragma unroll
    for (int mi = 0; mi < 2; mi++)
#pragma unroll
        for (int nj = 0; nj < 4; nj++)
#pragma unroll
            for (int q = 0; q < 4; q++) acc[mi][nj][q] = 0.f;

    // prefetch kt = 0 into buffer 0
    {
        uint32_t dA = (uint32_t)__cvta_generic_to_shared(&As[0][arow * APITCH + acol]);
        cp16(dA, aSrc); cp16(dA + 16, aSrc + 4);
        uint32_t dW = (uint32_t)__cvta_generic_to_shared(&Ws[0][wrow * APITCH + wcol]);
        cp16(dW, wSrc);
        CP_COMMIT();
    }

    int buf = 0;
#pragma unroll 1
    for (int kt = 0; kt < CH; kt += 16, buf ^= 1) {
        if (kt + 16 < CH) {
            uint32_t dA = (uint32_t)__cvta_generic_to_shared(&As[buf ^ 1][arow * APITCH + acol]);
            cp16(dA, aSrc + kt + 16); cp16(dA + 16, aSrc + kt + 20);
            uint32_t dW = (uint32_t)__cvta_generic_to_shared(&Ws[buf ^ 1][wrow * APITCH + wcol]);
            cp16(dW, wSrc + kt + 16);
            CP_COMMIT();
            CP_WAIT(1);
        } else {
            CP_WAIT(0);
        }
        __syncthreads();

#pragma unroll
        for (int k8 = 0; k8 < 16; k8 += 8) {
            uint32_t ah[2][4], al[2][4];
#pragma unroll
            for (int mi = 0; mi < 2; mi++) {
                const float* base = &As[buf][(wm * 32 + mi * 16) * APITCH + k8];
                split1(base[(g    ) * APITCH + tg    ], ah[mi][0], al[mi][0]);
                split1(base[(g + 8) * APITCH + tg    ], ah[mi][1], al[mi][1]);
                split1(base[(g    ) * APITCH + tg + 4], ah[mi][2], al[mi][2]);
                split1(base[(g + 8) * APITCH + tg + 4], ah[mi][3], al[mi][3]);
            }
            uint32_t bh_[4][2], bl_[4][2];
#pragma unroll
            for (int nj = 0; nj < 4; nj++) {
                const float* base = &Ws[buf][(wn * 32 + nj * 8 + g) * APITCH + k8];
                split1(base[tg    ], bh_[nj][0], bl_[nj][0]);
                split1(base[tg + 4], bh_[nj][1], bl_[nj][1]);
            }
#pragma unroll
            for (int mi = 0; mi < 2; mi++)
#pragma unroll
                for (int nj = 0; nj < 4; nj++)
                    mma3(acc[mi][nj], ah[mi], al[mi], bh_[nj], bl_[nj]);
        }
        __syncthreads();
    }

    // Epilogue
#pragma unroll
    for (int mi = 0; mi < 2; mi++) {
        const int r0 = rowBase + wm * 32 + mi * 16 + g;
        const int r1 = r0 + 8;
#pragma unroll
        for (int nj = 0; nj < 4; nj++) {
            float* cc = acc[mi][nj];
            const int colLoc = wn * 32 + nj * 8 + tg * 2;   // 0..63 inside n-tile
            if (mode == 0) {
                const int h = blockIdx.x;                    // 64-wide n-tile == one head
                const int b0 = r0 >> 10, n0_ = r0 & 1023;
                const int b1 = r1 >> 10, n1_ = r1 & 1023;
                float2 v0 = make_float2(cc[0] * QSCALE, cc[1] * QSCALE);
                float2 v1 = make_float2(cc[2] * QSCALE, cc[3] * QSCALE);
                *(float2*)&g_Qp[(((size_t)(b0*NH + h)*SEQ_N + n0_) << 6) + colLoc] = v0;
                *(float2*)&g_Qp[(((size_t)(b1*NH + h)*SEQ_N + n1_) << 6) + colLoc] = v1;
            } else if (mode == 1) {
                const int bx = blockIdx.x;
                float* dst = (bx >= NH) ? g_V : g_K;
                const int h = bx % NH;
                const int b0 = r0 >> 11, m0_ = r0 & 2047;
                const int b1 = r1 >> 11, m1_ = r1 & 2047;
                *(float2*)&dst[(((size_t)(b0*NH + h)*SEQ_M + m0_) << 6) + colLoc] =
                    make_float2(cc[0], cc[1]);
                *(float2*)&dst[(((size_t)(b1*NH + h)*SEQ_M + m1_) << 6) + colLoc] =
                    make_float2(cc[2], cc[3]);
            } else {
                const int col = oBase + colLoc;
                float2 bi = *(const float2*)(bias + col);
                *(float2*)&out[(size_t)r0 * CH + col] = make_float2(cc[0] + bi.x, cc[1] + bi.y);
                *(float2*)&out[(size_t)r1 * CH + col] = make_float2(cc[2] + bi.x, cc[3] + bi.y);
            }
        }
    }
}

// ---------------------------------------------------------------------------
// Flash attention with tf32 mma (3x split). 128 threads = 4 warps, each warp
// owns 16 q-rows (row reductions stay intra-warp). Q frags split once into
// registers; K/V/P staged in smem with conflict-free pitches.
// grid = (N/64, B*H)
// ---------------------------------------------------------------------------
#define KP 68
#define VP 72
#define PP 68
#define FA_SMEM ((64*KP + 64*VP + 64*PP) * (int)sizeof(float))   // 53248 B

__global__ __launch_bounds__(128)
void flash_mma(const int* __restrict__ mask)
{
    extern __shared__ float sm[];
    float* Ks = sm;
    float* Vs = sm + 64 * KP;
    float* Ps = sm + 64 * KP + 64 * VP;

    const int tid  = threadIdx.x;
    const int warp = tid >> 5, lane = tid & 31;
    const int g = lane >> 2, tg = lane & 3;
    const int bh = blockIdx.y, b = bh / NH, h = bh % NH;
    const int n0 = blockIdx.x * 64;
    const int rb = warp * 16;

    // Stage Q tile through Ks, then split fragments into registers
    {
        const float* Qg = g_Qp + ((size_t)bh * SEQ_N + n0) * HD;
        for (int idx = tid; idx < 64 * 16; idx += 128) {
            int r = idx >> 4, c4 = (idx & 15) * 4;
            *(float4*)&Ks[r * KP + c4] = *(const float4*)(Qg + r * HD + c4);
        }
    }
    __syncthreads();
    uint32_t qh[8][4], ql[8][4];
#pragma unroll
    for (int k8 = 0; k8 < 8; k8++) {
        split1(Ks[(rb + g    ) * KP + k8*8 + tg    ], qh[k8][0], ql[k8][0]);
        split1(Ks[(rb + g + 8) * KP + k8*8 + tg    ], qh[k8][1], ql[k8][1]);
        split1(Ks[(rb + g    ) * KP + k8*8 + tg + 4], qh[k8][2], ql[k8][2]);
        split1(Ks[(rb + g + 8) * KP + k8*8 + tg + 4], qh[k8][3], ql[k8][3]);
    }

    float m0 = -INFINITY, m1 = -INFINITY, l0 = 0.f, l1 = 0.f;
    float o[8][4];
#pragma unroll
    for (int nj = 0; nj < 8; nj++)
#pragma unroll
        for (int q = 0; q < 4; q++) o[nj][q] = 0.f;

    const int* mrow0 = mask + ((size_t)b * SEQ_N + n0 + rb + g) * SEQ_M;
    const int* mrow1 = mrow0 + (size_t)8 * SEQ_M;
    const float* Kg = g_K + (size_t)bh * SEQ_M * HD;
    const float* Vg = g_V + (size_t)bh * SEQ_M * HD;

#pragma unroll 1
    for (int mt = 0; mt < SEQ_M; mt += 64) {
        __syncthreads();   // all warps done with previous Ks/Vs/Ps
        for (int idx = tid; idx < 64 * 16; idx += 128) {
            int r = idx >> 4, c4 = (idx & 15) * 4;
            *(float4*)&Ks[r * KP + c4] = *(const float4*)(Kg + (size_t)(mt + r) * HD + c4);
            *(float4*)&Vs[r * VP + c4] = *(const float4*)(Vg + (size_t)(mt + r) * HD + c4);
        }
        __syncthreads();

        // S = Q @ K^T   (per warp: 16 rows x 64 cols)
        float s[8][4];
#pragma unroll
        for (int nj = 0; nj < 8; nj++)
#pragma unroll
            for (int q = 0; q < 4; q++) s[nj][q] = 0.f;

#pragma unroll
        for (int k8 = 0; k8 < 8; k8++) {
#pragma unroll
            for (int nj = 0; nj < 8; nj++) {
                uint32_t kbh[2], kbl[2];
                split1(Ks[(nj*8 + g) * KP + k8*8 + tg    ], kbh[0], kbl[0]);
                split1(Ks[(nj*8 + g) * KP + k8*8 + tg + 4], kbh[1], kbl[1]);
                mma3(s[nj], qh[k8], ql[k8], kbh, kbl);
            }
        }

        // mask
#pragma unroll
        for (int nj = 0; nj < 8; nj++) {
            int2 mk0 = *(const int2*)(mrow0 + mt + nj*8 + tg*2);
            int2 mk1 = *(const int2*)(mrow1 + mt + nj*8 + tg*2);
            if (!mk0.x) s[nj][0] = NEGV;
            if (!mk0.y) s[nj][1] = NEGV;
            if (!mk1.x) s[nj][2] = NEGV;
            if (!mk1.y) s[nj][3] = NEGV;
        }

        // online softmax (rows live in 4 lanes: shfl over lanes 1,2)
        float tm0 = -INFINITY, tm1 = -INFINITY;
#pragma unroll
        for (int nj = 0; nj < 8; nj++) {
            tm0 = fmaxf(tm0, fmaxf(s[nj][0], s[nj][1]));
            tm1 = fmaxf(tm1, fmaxf(s[nj][2], s[nj][3]));
        }
        tm0 = fmaxf(tm0, __shfl_xor_sync(0xffffffffu, tm0, 1));
        tm0 = fmaxf(tm0, __shfl_xor_sync(0xffffffffu, tm0, 2));
        tm1 = fmaxf(tm1, __shfl_xor_sync(0xffffffffu, tm1, 1));
        tm1 = fmaxf(tm1, __shfl_xor_sync(0xffffffffu, tm1, 2));
        float mn0 = fmaxf(m0, tm0), mn1 = fmaxf(m1, tm1);
        float c0 = __expf(m0 - mn0), c1 = __expf(m1 - mn1);
        float ts0 = 0.f, ts1 = 0.f;
#pragma unroll
        for (int nj = 0; nj < 8; nj++) {
            float p0 = __expf(s[nj][0] - mn0), p1 = __expf(s[nj][1] - mn0);
            float p2 = __expf(s[nj][2] - mn1), p3 = __expf(s[nj][3] - mn1);
            ts0 += p0 + p1; ts1 += p2 + p3;
            *(float2*)&Ps[(rb + g    ) * PP + nj*8 + tg*2] = make_float2(p0, p1);
            *(float2*)&Ps[(rb + g + 8) * PP + nj*8 + tg*2] = make_float2(p2, p3);
        }
        ts0 += __shfl_xor_sync(0xffffffffu, ts0, 1);
        ts0 += __shfl_xor_sync(0xffffffffu, ts0, 2);
        ts1 += __shfl_xor_sync(0xffffffffu, ts1, 1);
        ts1 += __shfl_xor_sync(0xffffffffu, ts1, 2);
        l0 = l0 * c0 + ts0; m0 = mn0;
        l1 = l1 * c1 + ts1; m1 = mn1;
#pragma unroll
        for (int nj = 0; nj < 8; nj++) {
            o[nj][0] *= c0; o[nj][1] *= c0;
            o[nj][2] *= c1; o[nj][3] *= c1;
        }
        __syncwarp();   // P rows are warp-private; make stores visible in-warp

        // O += P @ V
#pragma unroll
        for (int k8 = 0; k8 < 8; k8++) {
            uint32_t pah[4], pal[4];
            split1(Ps[(rb + g    ) * PP + k8*8 + tg    ], pah[0], pal[0]);
            split1(Ps[(rb + g + 8) * PP + k8*8 + tg    ], pah[1], pal[1]);
            split1(Ps[(rb + g    ) * PP + k8*8 + tg + 4], pah[2], pal[2]);
            split1(Ps[(rb + g + 8) * PP + k8*8 + tg + 4], pah[3], pal[3]);
#pragma unroll
            for (int nj = 0; nj < 8; nj++) {
                uint32_t vbh[2], vbl[2];
                split1(Vs[(k8*8 + tg    ) * VP + nj*8 + g], vbh[0], vbl[0]);
                split1(Vs[(k8*8 + tg + 4) * VP + nj*8 + g], vbh[1], vbl[1]);
                mma3(o[nj], pah, pal, vbh, vbl);
            }
        }
    }

    // normalize + write X[b, n, h*64 + d]
    float inv0 = 1.f / l0, inv1 = 1.f / l1;
    float* X0 = g_X + ((size_t)b * SEQ_N + n0 + rb + g) * CH + h * HD;
    float* X1 = X0 + (size_t)8 * CH;
#pragma unroll
    for (int nj = 0; nj < 8; nj++) {
        *(float2*)(X0 + nj*8 + tg*2) = make_float2(o[nj][0]*inv0, o[nj][1]*inv0);
        *(float2*)(X1 + nj*8 + tg*2) = make_float2(o[nj][2]*inv1, o[nj][3]*inv1);
    }
}

// ---------------------------------------------------------------------------
extern "C" void kernel_launch(void* const* d_in, const int* in_sizes, int n_in,
                              void* d_out, int out_size)
{
    const float* q     = (const float*)d_in[0];   // [4,1024,768]
    const float* kv    = (const float*)d_in[1];   // [4,2048,768]
    const float* Wq    = (const float*)d_in[2];   // [768,768]
    const float* Wkv   = (const float*)d_in[3];   // [1536,768]
    const float* Wproj = (const float*)d_in[4];   // [768,768]
    const float* bproj = (const float*)d_in[5];   // [768]
    const int*   mask  = (const int*)d_in[6];     // [4,1,1024,2048]
    float* out = (float*)d_out;                   // [4,1024,768]

    cudaFuncSetAttribute(flash_mma,
                         cudaFuncAttributeMaxDynamicSharedMemorySize, FA_SMEM);

    // Q projection: rows = 4096, cols = 768
    gemm_mma<<<dim3(CH/64, (BB*SEQ_N)/128), 256>>>(q, Wq, 0, nullptr, nullptr);
    // KV projection: rows = 8192, cols = 1536
    gemm_mma<<<dim3((2*CH)/64, (BB*SEQ_M)/128), 256>>>(kv, Wkv, 1, nullptr, nullptr);
    // Fused masked-softmax attention
    flash_mma<<<dim3(SEQ_N/64, BB*NH), 128, FA_SMEM>>>(mask);
    // Output projection + bias
    gemm_mma<<<dim3(CH/64, (BB*SEQ_N)/128), 256>>>(nullptr, Wproj, 2, out, bproj);
}